// round 13
// baseline (speedup 1.0000x reference)
#include <cuda_runtime.h>
#include <math.h>

#define FULL 0xffffffffu

// ---------------------------------------------------------------------------
// Closed form (verified rounds 1-12): fold the trailing CNOT ring into the
// PauliZ masks; the measured state is a product state, so
//   <Z_w> = prod_{q in M_w} z_q,  M_w = {0..w} (w>=1), M_0 = {1..9}
//   RX-circuit: z = cos(h + theta) ; RY-circuit: z = cos(theta)*cos(h)
//
// THIS ROUND: 16 threads/row ("hex"), 2 rows/warp, 2048 blocks x 128 threads
// (262144 threads, occ ~86%, still a single wave). Minimal per-thread work:
// 2 LDG.128, 20 FFMA2, 25 reduce-shfl + quad epilogue. Completes the
// threads-per-row scaling curve (4 -> 8 -> 16) at the max-occupancy corner.
// Reduce: xor-1 full -> parity half -> xor-2/xor-4/xor-8 (all 16 row lanes
// end sum-complete; even lanes h[0..4], odd h[5..9]).
// Epilogue per quad covers all 10 wires: q0:{0,1,2} q1:{5,6,7} q2:{3,4}
// q3:{8,9}; one quad per row stores ((lane&12)==0).
// ---------------------------------------------------------------------------

__device__ __forceinline__ unsigned long long
fma_f32x2(unsigned long long a, unsigned long long bb, unsigned long long c) {
    unsigned long long d;
    asm("fma.rn.f32x2 %0, %1, %2, %3;" : "=l"(d) : "l"(a), "l"(bb), "l"(c));
    return d;
}

__global__ void __launch_bounds__(128)
qlstm_kernel(const float* __restrict__ x, const float* __restrict__ W,
             const float* __restrict__ b,
             const float* __restrict__ wf, const float* __restrict__ wi,
             const float* __restrict__ wu, const float* __restrict__ wo,
             float* __restrict__ out) {
    const int tid = threadIdx.x;
    const int oc  = tid & 15;                  // sixteenth within row
    const int row = (blockIdx.x * 128 + tid) >> 4;

    // ---- x loads: 2 x 16B granules per thread ----
    const longlong2* xp = reinterpret_cast<const longlong2*>(x) + (size_t)row * 32;
    longlong2 xv[2];
#pragma unroll
    for (int i = 0; i < 2; i++) xv[i] = xp[i * 16 + oc];

    // ---- GEMM: h = x[row] @ W^T, packed f32x2 FMA (8 cols per thread) ----
    const longlong2* Wp = reinterpret_cast<const longlong2*>(W);
    unsigned long long acc2[10];
#pragma unroll
    for (int o = 0; o < 10; o++) acc2[o] = 0ull;
#pragma unroll
    for (int i = 0; i < 2; i++) {
        const unsigned long long xlo = (unsigned long long)xv[i].x;
        const unsigned long long xhi = (unsigned long long)xv[i].y;
#pragma unroll
        for (int o = 0; o < 10; o++) {
            const longlong2 wv = __ldg(&Wp[o * 32 + i * 16 + oc]);
            acc2[o] = fma_f32x2(xlo, (unsigned long long)wv.x, acc2[o]);
            acc2[o] = fma_f32x2(xhi, (unsigned long long)wv.y, acc2[o]);
        }
    }
    float acc[10];
#pragma unroll
    for (int o = 0; o < 10; o++) {
        const float lo = __uint_as_float((unsigned)(acc2[o] & 0xffffffffull));
        const float hi = __uint_as_float((unsigned)(acc2[o] >> 32));
        acc[o] = lo + hi;
    }

    // ---- reduce: full xor-1, parity halves for xor-2/xor-4/xor-8 ----
#pragma unroll
    for (int o = 0; o < 10; o++) acc[o] += __shfl_xor_sync(FULL, acc[o], 1);

    const int p = oc & 1;                      // 0: outputs 0-4, 1: outputs 5-9
    float a[5];
#pragma unroll
    for (int j = 0; j < 5; j++) a[j] = p ? acc[5 + j] : acc[j];
#pragma unroll
    for (int j = 0; j < 5; j++) a[j] += __shfl_xor_sync(FULL, a[j], 2);
#pragma unroll
    for (int j = 0; j < 5; j++) a[j] += __shfl_xor_sync(FULL, a[j], 4);
#pragma unroll
    for (int j = 0; j < 5; j++) a[j] += __shfl_xor_sync(FULL, a[j], 8);
    // all 16 row-lanes complete: even lanes h[0..4], odd lanes h[5..9]

    // ---- quad epilogue: q0:{0,1,2} q1:{5,6,7} q2:{3,4} q3:{8,9} ----
    const int lane = tid & 31;
    const int q = lane & 3;
    const int nw = (q < 2) ? 3 : 2;
    const int j0 = (q < 2) ? 0 : 3;            // index into a[]
    const int w0 = 5 * p + j0;                 // first owned wire

    float myh[3], zf[3], zi[3], zu[3], zo[3];
#pragma unroll
    for (int j = 0; j < 3; j++) {
        if (j < nw) {
            const int w = w0 + j;
            const float h = ((j0 == 0) ? a[j] : a[3 + j]) + __ldg(b + w);
            myh[j] = h;
            const float ch = __cosf(h);
            zf[j] = __cosf(h + __ldg(wf + w));          // RX: cos(h + wf)
            zi[j] = __cosf(__ldg(wi + w)) * ch;         // RY: cos(wi)*cos(h)
            zu[j] = __cosf(h + __ldg(wu + w));
            zo[j] = __cosf(h + __ldg(wo + w));
        } else {
            myh[j] = 0.0f;
            zf[j] = zi[j] = zu[j] = zo[j] = 1.0f;
        }
    }

    // prefix composition along wire-order [q0, q2, q1, q3]:
    //   C(q0)=1; C(q2)=x2; C(q1)=x1*x3; C(q3)=x1*x2*x3
    // wire-0 special (q0): E0 = z1*z2 * x1*x2*x3
    float Ef[3], Ei[3], Eu[3], Eo[3];
#pragma unroll
    for (int c = 0; c < 4; c++) {
        const float* z = (c == 0) ? zf : (c == 1) ? zi : (c == 2) ? zu : zo;
        const float l1 = z[0], l2 = l1 * z[1], l3 = l2 * z[2];
        const float l  = (q < 2) ? l3 : l2;             // product of owned z's

        const float x1 = __shfl_xor_sync(FULL, l, 1);
        const float x2 = __shfl_xor_sync(FULL, l, 2);
        const float x3 = __shfl_xor_sync(FULL, x1, 2);
        const float p123 = x1 * x2 * x3;
        const float C = (q == 0) ? 1.0f : (q == 2) ? x2
                       : (q == 1) ? x1 * x3 : p123;

        float E0 = C * l1;
        if (q == 0) E0 = z[1] * z[2] * p123;            // wire 0: z1..z9
        const float E1 = C * l2, E2 = C * l3;

        if (c == 0)      { Ef[0] = E0; Ef[1] = E1; Ef[2] = E2; }
        else if (c == 1) { Ei[0] = E0; Ei[1] = E1; Ei[2] = E2; }
        else if (c == 2) { Eu[0] = E0; Eu[1] = E1; Eu[2] = E2; }
        else             { Eo[0] = E0; Eo[1] = E1; Eo[2] = E2; }
    }

    // ---- LSTM epilogue; one quad per row stores ----
    const bool writer = (lane & 12) == 0;
#pragma unroll
    for (int j = 0; j < 3; j++) {
        if (j < nw && writer) {
            const float ing = __fdividef(1.0f, 1.0f + __expf(-Ef[j]));
            const float fg  = __fdividef(1.0f, 1.0f + __expf(-Ei[j]));
            const float cg  = __fdividef(2.0f, 1.0f + __expf(-2.0f * Eu[j])) - 1.0f;
            const float og  = __fdividef(1.0f, 1.0f + __expf(-Eo[j]));
            const float nh  = fmaf(myh[j], fg, ing * cg);
            const float th  = __fdividef(2.0f, 1.0f + __expf(-2.0f * nh)) - 1.0f;
            out[row * 10 + w0 + j] = og * th;
        }
    }
}

extern "C" void kernel_launch(void* const* d_in, const int* in_sizes, int n_in,
                              void* d_out, int out_size) {
    const float* x  = (const float*)d_in[0];
    const float* W  = (const float*)d_in[1];
    const float* b  = (const float*)d_in[2];
    const float* wf = (const float*)d_in[3];
    const float* wi = (const float*)d_in[4];
    const float* wu = (const float*)d_in[5];
    const float* wo = (const float*)d_in[6];
    float* out = (float*)d_out;

    // 16384 rows x 16 threads = 262144 threads; 128/block -> 2048 blocks
    qlstm_kernel<<<2048, 128>>>(x, W, b, wf, wi, wu, wo, out);
}

// round 15
// speedup vs baseline: 1.1383x; 1.1383x over previous
#include <cuda_runtime.h>
#include <math.h>

#define FULL 0xffffffffu

// ---------------------------------------------------------------------------
// Closed form (verified rounds 1-13): fold the trailing CNOT ring into the
// PauliZ masks; the measured state is a product state, so
//   <Z_w> = prod_{q in M_w} z_q,  M_w = {0..w} (w>=1), M_0 = {1..9}
//   RX-circuit: z = cos(h + theta) ; RY-circuit: z = cos(theta)*cos(h)
//
// Layout (measured optimum): 8 threads/row octet, 4 rows/warp,
// 1024 blocks x 128 threads (131072 threads), single launch.
// GEMM: packed fma.rn.f32x2 on LDG.128 payloads (80 FFMA2).
// Epilogue parameter loads (b + 4 weight vectors) hoisted ABOVE the GEMM so
// their L1 latency overlaps the FMA block instead of the post-reduce path.
// Reduce: 30-shfl octet xor allreduce (redux.f32 rejected by ptxas/sm_100).
// Epilogue: quad ownership q0:{0,1,2} q1:{3,4,5} q2:{6,7,8} q3:{9};
// 3-shfl xor-gather prefix products; low quad of each octet stores.
// ---------------------------------------------------------------------------

__device__ __forceinline__ unsigned long long
fma_f32x2(unsigned long long a, unsigned long long bb, unsigned long long c) {
    unsigned long long d;
    asm("fma.rn.f32x2 %0, %1, %2, %3;" : "=l"(d) : "l"(a), "l"(bb), "l"(c));
    return d;
}

__global__ void __launch_bounds__(128)
qlstm_kernel(const float* __restrict__ x, const float* __restrict__ W,
             const float* __restrict__ b,
             const float* __restrict__ wf, const float* __restrict__ wi,
             const float* __restrict__ wu, const float* __restrict__ wo,
             float* __restrict__ out) {
    const int tid = threadIdx.x;
    const int oc  = tid & 7;                   // eighth within row
    const int row = (blockIdx.x * 128 + tid) >> 3;

    // ---- front-batched x loads: row = 32 x 16B granules ----
    const longlong2* xp = reinterpret_cast<const longlong2*>(x) + (size_t)row * 32;
    longlong2 xv[4];
#pragma unroll
    for (int i = 0; i < 4; i++) xv[i] = xp[i * 8 + oc];

    // ---- hoisted epilogue parameter loads (overlap with GEMM FMAs) ----
    const int lane = tid & 31;
    const int q = lane & 3;
    const int nw = (q < 3) ? 3 : 1;
    const int w0 = 3 * q;
    float pb[3], pf[3], pi[3], pu[3], po[3];
#pragma unroll
    for (int j = 0; j < 3; j++) {
        const int w = (j < nw) ? (w0 + j) : 0;
        pb[j] = __ldg(b + w);  pf[j] = __ldg(wf + w);  pi[j] = __ldg(wi + w);
        pu[j] = __ldg(wu + w); po[j] = __ldg(wo + w);
    }

    // ---- GEMM: h = x[row] @ W^T, packed f32x2 FMA ----
    const longlong2* Wp = reinterpret_cast<const longlong2*>(W);
    unsigned long long acc2[10];
#pragma unroll
    for (int o = 0; o < 10; o++) acc2[o] = 0ull;
#pragma unroll
    for (int i = 0; i < 4; i++) {
        const unsigned long long xlo = (unsigned long long)xv[i].x;
        const unsigned long long xhi = (unsigned long long)xv[i].y;
#pragma unroll
        for (int o = 0; o < 10; o++) {
            const longlong2 wv = __ldg(&Wp[o * 32 + i * 8 + oc]);
            acc2[o] = fma_f32x2(xlo, (unsigned long long)wv.x, acc2[o]);
            acc2[o] = fma_f32x2(xhi, (unsigned long long)wv.y, acc2[o]);
        }
    }
    float acc[10];
#pragma unroll
    for (int o = 0; o < 10; o++) {
        const float lo = __uint_as_float((unsigned)(acc2[o] & 0xffffffffull));
        const float hi = __uint_as_float((unsigned)(acc2[o] >> 32));
        acc[o] = lo + hi;
    }

    // ---- octet allreduce: all 8 lanes end with the full sums ----
#pragma unroll
    for (int o = 0; o < 10; o++) {
        acc[o] += __shfl_xor_sync(FULL, acc[o], 1);
        acc[o] += __shfl_xor_sync(FULL, acc[o], 2);
        acc[o] += __shfl_xor_sync(FULL, acc[o], 4);
    }

    // ---- quad epilogue: q0:{0,1,2} q1:{3,4,5} q2:{6,7,8} q3:{9} ----
    float myh[3], zf[3], zi[3], zu[3], zo[3];
#pragma unroll
    for (int j = 0; j < 3; j++) {
        float hv = acc[j];
        if (q == 1) hv = acc[3 + j];
        if (q == 2) hv = acc[6 + j];
        if (q == 3) hv = (j == 0) ? acc[9] : 0.0f;

        if (j < nw) {
            const float h = hv + pb[j];
            myh[j] = h;
            const float ch = __cosf(h);
            zf[j] = __cosf(h + pf[j]);          // RX: cos(h + wf)
            zi[j] = __cosf(pi[j]) * ch;         // RY: cos(wi)*cos(h)
            zu[j] = __cosf(h + pu[j]);
            zo[j] = __cosf(h + po[j]);
        } else {
            myh[j] = 0.0f;
            zf[j] = zi[j] = zu[j] = zo[j] = 1.0f;
        }
    }

    // per-circuit quad prefix products via 3-shfl xor-gather
    // C(q) = prod_{q'<q} l3(q'); wire-0 special: E0 = z1*z2 * x1*x2*x3
    float Ef[3], Ei[3], Eu[3], Eo[3];
#pragma unroll
    for (int c = 0; c < 4; c++) {
        const float* z = (c == 0) ? zf : (c == 1) ? zi : (c == 2) ? zu : zo;
        const float l1 = z[0], l2 = l1 * z[1], l3 = l2 * z[2];

        const float x1 = __shfl_xor_sync(FULL, l3, 1);
        const float x2 = __shfl_xor_sync(FULL, l3, 2);
        const float x3 = __shfl_xor_sync(FULL, x1, 2);
        const float p23  = x2 * x3;
        const float p123 = x1 * p23;
        const float C = (q == 0) ? 1.0f : (q == 1) ? x1 : (q == 2) ? p23 : p123;

        float E0 = C * l1;
        if (q == 0) E0 = z[1] * z[2] * p123;            // wire 0: z1..z9
        const float E1 = C * l2, E2 = C * l3;

        if (c == 0)      { Ef[0] = E0; Ef[1] = E1; Ef[2] = E2; }
        else if (c == 1) { Ei[0] = E0; Ei[1] = E1; Ei[2] = E2; }
        else if (c == 2) { Eu[0] = E0; Eu[1] = E1; Eu[2] = E2; }
        else             { Eo[0] = E0; Eo[1] = E1; Eo[2] = E2; }
    }

    // ---- LSTM epilogue; only the low quad of each octet stores ----
    const bool writer = (lane & 4) == 0;
#pragma unroll
    for (int j = 0; j < 3; j++) {
        if (j < nw && writer) {
            const float ing = __fdividef(1.0f, 1.0f + __expf(-Ef[j]));
            const float fg  = __fdividef(1.0f, 1.0f + __expf(-Ei[j]));
            const float cg  = __fdividef(2.0f, 1.0f + __expf(-2.0f * Eu[j])) - 1.0f;
            const float og  = __fdividef(1.0f, 1.0f + __expf(-Eo[j]));
            const float nh  = fmaf(myh[j], fg, ing * cg);
            const float th  = __fdividef(2.0f, 1.0f + __expf(-2.0f * nh)) - 1.0f;
            out[row * 10 + w0 + j] = og * th;
        }
    }
}

extern "C" void kernel_launch(void* const* d_in, const int* in_sizes, int n_in,
                              void* d_out, int out_size) {
    const float* x  = (const float*)d_in[0];
    const float* W  = (const float*)d_in[1];
    const float* b  = (const float*)d_in[2];
    const float* wf = (const float*)d_in[3];
    const float* wi = (const float*)d_in[4];
    const float* wu = (const float*)d_in[5];
    const float* wo = (const float*)d_in[6];
    float* out = (float*)d_out;

    // 16384 rows x 8 threads = 131072 threads; 128/block -> 1024 blocks
    qlstm_kernel<<<1024, 128>>>(x, W, b, wf, wi, wu, wo, out);
}

// round 16
// speedup vs baseline: 1.1449x; 1.0058x over previous
#include <cuda_runtime.h>
#include <math.h>

#define FULL 0xffffffffu

// ---------------------------------------------------------------------------
// FINAL (converged, measured optimum = round-6 kernel, 10.24 us).
//
// Math (verified rounds 1-6 and held at rel_err ~2.6e-7 throughout):
// fold the trailing CNOT ring into the PauliZ masks (GF(2)-linear), the
// measured state is then a product state, so
//   <Z_w> = prod_{q in M_w} z_q,  M_w = {0..w} (w>=1), M_0 = {1..9}
//   RX-circuit: z = cos(h + theta) ; RY-circuit: z = cos(theta)*cos(h)
// This collapses the 4x 1024-amplitude statevector simulations (232 us at
// round 1) to 5 cosines/wire + 4 prefix products.
//
// Layout: 8 threads/row octet, 4 rows/warp, 1024 blocks x 128 threads
// (131072 threads, single wave), single kernel launch, no smem, no syncs:
//  - x via streaming __ldcs float4 (read-once, coalesced, MLP=4)
//  - W via __ldg (L1-resident, coalescer dedups the 4-lane-duplicate pattern)
//  - octet xor-allreduce (30 shfl) -> all lanes hold h[0..9]
//  - quad epilogue q0:{0,1,2} q1:{3,4,5} q2:{6,7,8} q3:{9}, fast trig,
//    3-shfl xor-gather prefix products, low quad stores.
//
// Exploration record (all within noise of this, 10.1-11.1 us): threads/row
// {4,8,16}, blocks {128,256,512}, occ 20-86%, FFMA2 GEMM, load hoisting,
// W-load batching, smem staging, parity-split reduces. f32 REDUX rejected by
// ptxas on sm_100. Floor is launch/ramp + latency-chain bound, not any pipe.
// ---------------------------------------------------------------------------
__global__ void __launch_bounds__(128)
qlstm_kernel(const float* __restrict__ x, const float* __restrict__ W,
             const float* __restrict__ b,
             const float* __restrict__ wf, const float* __restrict__ wi,
             const float* __restrict__ wu, const float* __restrict__ wo,
             float* __restrict__ out) {
    const int tid = threadIdx.x;
    const int oc  = tid & 7;                   // eighth within row
    const int row = (blockIdx.x * 128 + tid) >> 3;

    // ---- x loads first: streaming hint (read-once), front-batched ----
    const float4* x4 = reinterpret_cast<const float4*>(x) + (size_t)row * 32;
    float4 xv[4];
#pragma unroll
    for (int i = 0; i < 4; i++) xv[i] = __ldcs(&x4[i * 8 + oc]);

    // ---- GEMM: h = x[row] @ W^T (16 cols per thread), W via L1 ----
    const float4* W4 = reinterpret_cast<const float4*>(W);
    float acc[10];
#pragma unroll
    for (int o = 0; o < 10; o++) acc[o] = 0.0f;
#pragma unroll
    for (int i = 0; i < 4; i++) {
#pragma unroll
        for (int o = 0; o < 10; o++) {
            const float4 wv = __ldg(&W4[o * 32 + i * 8 + oc]);
            acc[o] = fmaf(xv[i].x, wv.x,
                     fmaf(xv[i].y, wv.y,
                     fmaf(xv[i].z, wv.z,
                     fmaf(xv[i].w, wv.w, acc[o]))));
        }
    }
    // octet allreduce: all 8 lanes end with the full sums
#pragma unroll
    for (int o = 0; o < 10; o++) {
        acc[o] += __shfl_xor_sync(FULL, acc[o], 1);
        acc[o] += __shfl_xor_sync(FULL, acc[o], 2);
        acc[o] += __shfl_xor_sync(FULL, acc[o], 4);
    }

    // ---- quad-wide epilogue (both quads of the octet run it identically) --
    const int lane = tid & 31;
    const int q = lane & 3;
    const int nw = (q < 3) ? 3 : 1;
    const int w0 = 3 * q;

    float myh[3], zf[3], zi[3], zu[3], zo[3];
#pragma unroll
    for (int j = 0; j < 3; j++) {
        float hv = acc[j];
        if (q == 1) hv = acc[3 + j];
        if (q == 2) hv = acc[6 + j];
        if (q == 3) hv = (j == 0) ? acc[9] : 0.0f;

        if (j < nw) {
            const int w = w0 + j;
            const float h = hv + __ldg(b + w);
            myh[j] = h;
            float sh, ch;
            __sincosf(h, &sh, &ch);
            float sf_, cf_, su_, cu_, so_, co_;
            __sincosf(__ldg(wf + w), &sf_, &cf_);
            __sincosf(__ldg(wu + w), &su_, &cu_);
            __sincosf(__ldg(wo + w), &so_, &co_);
            zf[j] = ch * cf_ - sh * sf_;        // RX: cos(h + wf)
            zi[j] = __cosf(__ldg(wi + w)) * ch; // RY: cos(wi) * cos(h)
            zu[j] = ch * cu_ - sh * su_;
            zo[j] = ch * co_ - sh * so_;
        } else {
            myh[j] = 0.0f;
            zf[j] = zi[j] = zu[j] = zo[j] = 1.0f;
        }
    }

    // per-circuit quad prefix products via 3-shfl xor-gather
    // C(q) = prod_{q'<q} l3(q'); wire-0 special: E0 = z1*z2 * x1*x2*x3
    float Ef[3], Ei[3], Eu[3], Eo[3];
#pragma unroll
    for (int c = 0; c < 4; c++) {
        const float* z = (c == 0) ? zf : (c == 1) ? zi : (c == 2) ? zu : zo;
        const float l1 = z[0], l2 = l1 * z[1], l3 = l2 * z[2];

        const float x1 = __shfl_xor_sync(FULL, l3, 1);
        const float x2 = __shfl_xor_sync(FULL, l3, 2);
        const float x3 = __shfl_xor_sync(FULL, x1, 2);
        const float p23  = x2 * x3;
        const float p123 = x1 * p23;
        const float C = (q == 0) ? 1.0f : (q == 1) ? x1 : (q == 2) ? p23 : p123;

        float E0 = C * l1;
        if (q == 0) E0 = z[1] * z[2] * p123;            // wire 0: z1..z9
        const float E1 = C * l2, E2 = C * l3;

        if (c == 0)      { Ef[0] = E0; Ef[1] = E1; Ef[2] = E2; }
        else if (c == 1) { Ei[0] = E0; Ei[1] = E1; Ei[2] = E2; }
        else if (c == 2) { Eu[0] = E0; Eu[1] = E1; Eu[2] = E2; }
        else             { Eo[0] = E0; Eo[1] = E1; Eo[2] = E2; }
    }

    // ---- LSTM epilogue; only the low quad of each octet stores ----
    const bool writer = (lane & 4) == 0;
#pragma unroll
    for (int j = 0; j < 3; j++) {
        if (j < nw && writer) {
            const float ing = __fdividef(1.0f, 1.0f + __expf(-Ef[j]));
            const float fg  = __fdividef(1.0f, 1.0f + __expf(-Ei[j]));
            const float cg  = __fdividef(2.0f, 1.0f + __expf(-2.0f * Eu[j])) - 1.0f;
            const float og  = __fdividef(1.0f, 1.0f + __expf(-Eo[j]));
            const float nh  = fmaf(myh[j], fg, ing * cg);
            const float th  = __fdividef(2.0f, 1.0f + __expf(-2.0f * nh)) - 1.0f;
            out[row * 10 + w0 + j] = og * th;
        }
    }
}

extern "C" void kernel_launch(void* const* d_in, const int* in_sizes, int n_in,
                              void* d_out, int out_size) {
    const float* x  = (const float*)d_in[0];
    const float* W  = (const float*)d_in[1];
    const float* b  = (const float*)d_in[2];
    const float* wf = (const float*)d_in[3];
    const float* wi = (const float*)d_in[4];
    const float* wu = (const float*)d_in[5];
    const float* wo = (const float*)d_in[6];
    float* out = (float*)d_out;

    // 16384 rows x 8 threads = 131072 threads; 128/block -> 1024 blocks
    qlstm_kernel<<<1024, 128>>>(x, W, b, wf, wi, wu, wo, out);
}

// round 17
// speedup vs baseline: 1.1550x; 1.0088x over previous
#include <cuda_runtime.h>
#include <math.h>

#define FULL 0xffffffffu

// ---------------------------------------------------------------------------
// Closed form (verified rounds 1-16): fold the trailing CNOT ring into the
// PauliZ masks (GF(2)-linear); the measured state is a product state, so
//   <Z_w> = prod_{q in M_w} z_q,  M_w = {0..w} (w>=1), M_0 = {1..9}
//   RX-circuit: z = cos(h + theta) ; RY-circuit: z = cos(theta)*cos(h)
//
// Layout (measured optimum): 8 threads/row octet, 4 rows/warp,
// 1024 blocks x 128 threads (131072 threads), single launch, no smem/syncs.
// Minimum-issue variant:
//  - GEMM: packed fma.rn.f32x2 on LDG.128 payloads (80 FFMA2, verified R9).
//  - Octet xor-allreduce (30 shfl) -> all lanes hold h[0..9].
//  - CIRCUIT-SPLIT epilogue (branchless): low quad computes circuits (f,i),
//    high quad (u,o) via per-lane weight-pointer select; the RY circuit is
//    folded in as zB = cos(hB + wB)*mB with hB = g?h:0, mB = g?1:cos(h).
//    2 scans/lane instead of 4; xor-4 exchange returns (Eu,Eo) to writers.
//  - Quad ownership q0:{0,1,2} q1:{3,4,5} q2:{6,7,8} q3:{9}; low quad stores.
// ---------------------------------------------------------------------------

__device__ __forceinline__ unsigned long long
fma_f32x2(unsigned long long a, unsigned long long bb, unsigned long long c) {
    unsigned long long d;
    asm("fma.rn.f32x2 %0, %1, %2, %3;" : "=l"(d) : "l"(a), "l"(bb), "l"(c));
    return d;
}

__global__ void __launch_bounds__(128)
qlstm_kernel(const float* __restrict__ x, const float* __restrict__ W,
             const float* __restrict__ b,
             const float* __restrict__ wf, const float* __restrict__ wi,
             const float* __restrict__ wu, const float* __restrict__ wo,
             float* __restrict__ out) {
    const int tid = threadIdx.x;
    const int oc  = tid & 7;                   // eighth within row
    const int row = (blockIdx.x * 128 + tid) >> 3;

    // ---- front-batched x loads: row = 32 x 16B granules ----
    const longlong2* xp = reinterpret_cast<const longlong2*>(x) + (size_t)row * 32;
    longlong2 xv[4];
#pragma unroll
    for (int i = 0; i < 4; i++) xv[i] = xp[i * 8 + oc];

    // ---- GEMM: h = x[row] @ W^T, packed f32x2 FMA ----
    const longlong2* Wp = reinterpret_cast<const longlong2*>(W);
    unsigned long long acc2[10];
#pragma unroll
    for (int o = 0; o < 10; o++) acc2[o] = 0ull;
#pragma unroll
    for (int i = 0; i < 4; i++) {
        const unsigned long long xlo = (unsigned long long)xv[i].x;
        const unsigned long long xhi = (unsigned long long)xv[i].y;
#pragma unroll
        for (int o = 0; o < 10; o++) {
            const longlong2 wv = __ldg(&Wp[o * 32 + i * 8 + oc]);
            acc2[o] = fma_f32x2(xlo, (unsigned long long)wv.x, acc2[o]);
            acc2[o] = fma_f32x2(xhi, (unsigned long long)wv.y, acc2[o]);
        }
    }
    float acc[10];
#pragma unroll
    for (int o = 0; o < 10; o++) {
        const float lo = __uint_as_float((unsigned)(acc2[o] & 0xffffffffull));
        const float hi = __uint_as_float((unsigned)(acc2[o] >> 32));
        acc[o] = lo + hi;
    }
    // octet allreduce: all 8 lanes end with the full sums
#pragma unroll
    for (int o = 0; o < 10; o++) {
        acc[o] += __shfl_xor_sync(FULL, acc[o], 1);
        acc[o] += __shfl_xor_sync(FULL, acc[o], 2);
        acc[o] += __shfl_xor_sync(FULL, acc[o], 4);
    }

    // ---- circuit-split quad epilogue ----
    const int lane = tid & 31;
    const int q = lane & 3;
    const int g = (lane >> 2) & 1;             // 0: circuits (f,i); 1: (u,o)
    const int nw = (q < 3) ? 3 : 1;
    const int w0 = 3 * q;

    // per-quad circuit weights (branchless pointer select)
    const float* pA = g ? wu : wf;             // circuit A: always RX
    const float* pB = g ? wo : wi;             // circuit B: RX (g=1) / RY (g=0)

    float myh[3], zA[3], zB[3];
#pragma unroll
    for (int j = 0; j < 3; j++) {
        float hv = acc[j];
        if (q == 1) hv = acc[3 + j];
        if (q == 2) hv = acc[6 + j];
        if (q == 3) hv = (j == 0) ? acc[9] : 0.0f;

        if (j < nw) {
            const int w = w0 + j;
            const float h = hv + __ldg(b + w);
            myh[j] = h;
            const float ch = __cosf(h);
            zA[j] = __cosf(h + __ldg(pA + w));                   // RX
            const float hB = g ? h : 0.0f;
            const float mB = g ? 1.0f : ch;
            zB[j] = __cosf(hB + __ldg(pB + w)) * mB;             // RX or RY
        } else {
            myh[j] = 0.0f;
            zA[j] = zB[j] = 1.0f;
        }
    }

    // two quad prefix-product scans (3-shfl xor-gather each)
    // C(q) = prod_{q'<q} l3(q'); wire-0 special: E0 = z1*z2 * x1*x2*x3
    float EA[3], EB[3];
#pragma unroll
    for (int c = 0; c < 2; c++) {
        const float* z = (c == 0) ? zA : zB;
        const float l1 = z[0], l2 = l1 * z[1], l3 = l2 * z[2];

        const float x1 = __shfl_xor_sync(FULL, l3, 1);
        const float x2 = __shfl_xor_sync(FULL, l3, 2);
        const float x3 = __shfl_xor_sync(FULL, x1, 2);
        const float p23  = x2 * x3;
        const float p123 = x1 * p23;
        const float C = (q == 0) ? 1.0f : (q == 1) ? x1 : (q == 2) ? p23 : p123;

        float E0 = C * l1;
        if (q == 0) E0 = z[1] * z[2] * p123;            // wire 0: z1..z9
        const float E1 = C * l2, E2 = C * l3;

        if (c == 0) { EA[0] = E0; EA[1] = E1; EA[2] = E2; }
        else        { EB[0] = E0; EB[1] = E1; EB[2] = E2; }
    }

    // exchange across quads (xor 4): writers receive (Eu, Eo) from high quad
    float EuX[3], EoX[3];
#pragma unroll
    for (int j = 0; j < 3; j++) {
        EuX[j] = __shfl_xor_sync(FULL, EA[j], 4);
        EoX[j] = __shfl_xor_sync(FULL, EB[j], 4);
    }

    // ---- LSTM epilogue; low quad (g==0) holds (Ef,Ei) + received (Eu,Eo) --
#pragma unroll
    for (int j = 0; j < 3; j++) {
        if (j < nw && g == 0) {
            const float ing = __fdividef(1.0f, 1.0f + __expf(-EA[j]));   // f
            const float fg  = __fdividef(1.0f, 1.0f + __expf(-EB[j]));   // i
            const float cg  = __fdividef(2.0f, 1.0f + __expf(-2.0f * EuX[j])) - 1.0f;
            const float og  = __fdividef(1.0f, 1.0f + __expf(-EoX[j]));
            const float nh  = fmaf(myh[j], fg, ing * cg);
            const float th  = __fdividef(2.0f, 1.0f + __expf(-2.0f * nh)) - 1.0f;
            out[row * 10 + w0 + j] = og * th;
        }
    }
}

extern "C" void kernel_launch(void* const* d_in, const int* in_sizes, int n_in,
                              void* d_out, int out_size) {
    const float* x  = (const float*)d_in[0];
    const float* W  = (const float*)d_in[1];
    const float* b  = (const float*)d_in[2];
    const float* wf = (const float*)d_in[3];
    const float* wi = (const float*)d_in[4];
    const float* wu = (const float*)d_in[5];
    const float* wo = (const float*)d_in[6];
    float* out = (float*)d_out;

    // 16384 rows x 8 threads = 131072 threads; 128/block -> 1024 blocks
    qlstm_kernel<<<1024, 128>>>(x, W, b, wf, wi, wu, wo, out);
}